// round 4
// baseline (speedup 1.0000x reference)
#include <cuda_runtime.h>
#include <cuda_bf16.h>
#include <math.h>

#define NN 512
#define CC 256
#define HWP 196          // 14*14
#define CKTOT 2304       // C*9
#define TC 8             // input-channel chunk in smem

// ---------------- scratch (static device globals; no allocation) -------------
__device__ float g_Wc[CKTOT * CC];     // combined char weights   [ck][o]
__device__ float g_Wt[CKTOT * CC];     // combined text weights   [ck][o]
__device__ float g_Wf[CKTOT * CC];     // combined fuse weights   [ck][o]
__device__ float g_branch[NN * CC * HWP]; // branch conv output (103MB)
__device__ int   g_members[NN * NN];   // member lists per proposal
__device__ int   g_cnt[NN];
__device__ float g_inv[NN];

// ---------------- 1) box overlap mask / member lists -------------------------
__global__ void mask_kernel(const float* __restrict__ boxes) {
    int i = blockIdx.x * blockDim.x + threadIdx.x;
    if (i >= NN) return;
    float ax0 = boxes[i * 4 + 0], ay0 = boxes[i * 4 + 1];
    float ax1 = boxes[i * 4 + 2], ay1 = boxes[i * 4 + 3];
    int c = 0;
    for (int j = 0; j < NN; j++) {
        float bx0 = boxes[j * 4 + 0], by0 = boxes[j * 4 + 1];
        float bx1 = boxes[j * 4 + 2], by1 = boxes[j * 4 + 3];
        float ltx = fmaxf(ax0, bx0), lty = fmaxf(ay0, by0);
        float rbx = fminf(ax1, bx1), rby = fminf(ay1, by1);
        float w = fmaxf(rbx - ltx, 0.0f);
        float h = fmaxf(rby - lty, 0.0f);
        float inter = w * h;
        float areaj = (bx1 - bx0) * (by1 - by0);
        if (inter / areaj > 0.9f) { g_members[i * NN + c] = j; c++; }
    }
    g_cnt[i] = c;
    g_inv[i] = 1.0f / (float)c;
}

// ---------------- 2) fold conv1x1 into conv3x3 weights ------------------------
// Wo[ck][o] = sum_m W1[o][m] * W3[m][ck],   ck = c*9 + k
__global__ void combine_kernel(const float* __restrict__ Wc3, const float* __restrict__ Wc1,
                               const float* __restrict__ Wt3, const float* __restrict__ Wt1,
                               const float* __restrict__ Wf3, const float* __restrict__ Wf1) {
    const float *W3, *W1;
    float* Wo;
    if (blockIdx.z == 0)      { W3 = Wc3; W1 = Wc1; Wo = g_Wc; }
    else if (blockIdx.z == 1) { W3 = Wt3; W1 = Wt1; Wo = g_Wt; }
    else                      { W3 = Wf3; W1 = Wf1; Wo = g_Wf; }

    int ckb = blockIdx.x * 32;   // 72 tiles of 32 over 2304
    int ob  = blockIdx.y * 64;   // 4 tiles of 64 over 256
    int tid = threadIdx.x;       // 256 threads
    int ck_l = tid >> 3;         // 0..31
    int og   = tid & 7;          // 0..7 -> 8 contiguous outputs

    __shared__ __align__(16) float As[32 * 32];   // [m][ck]
    __shared__ __align__(16) float Bs[32 * 64];   // [m][o]

    float acc[8];
#pragma unroll
    for (int j = 0; j < 8; j++) acc[j] = 0.0f;

    for (int mb = 0; mb < 256; mb += 32) {
        __syncthreads();
        for (int idx = tid; idx < 1024; idx += 256) {
            int m = idx >> 5, ck = idx & 31;
            As[idx] = W3[(mb + m) * CKTOT + ckb + ck];
        }
        {
            int o  = tid & 63;
            int m8 = (tid >> 6) * 8;
#pragma unroll
            for (int mi = 0; mi < 8; mi++)
                Bs[(m8 + mi) * 64 + o] = W1[(ob + o) * 256 + mb + m8 + mi];
        }
        __syncthreads();
#pragma unroll
        for (int m = 0; m < 32; m++) {
            float a = As[m * 32 + ck_l];
            float b[8];
            *(float4*)&b[0] = *(const float4*)&Bs[m * 64 + og * 8];
            *(float4*)&b[4] = *(const float4*)&Bs[m * 64 + og * 8 + 4];
#pragma unroll
            for (int j = 0; j < 8; j++) acc[j] = fmaf(a, b[j], acc[j]);
        }
    }
    float* po = &Wo[(ckb + ck_l) * 256 + ob + og * 8];
    *(float4*)po       = *(const float4*)&acc[0];
    *(float4*)(po + 4) = *(const float4*)&acc[4];
}

// ---------------- 3) main conv3x3 kernel --------------------------------------
// MODE 0: branch conv. input = (class!=0) ? x[n] : gather-avg ; W = Wc or Wt ; out -> g_branch
// MODE 1: fuse conv.   input = g_branch[n] + x[n] + gc[n]     ; W = Wf        ; out -> d_out (BN+ReLU)
// grid (4 oc-tiles, 512 samples), block 224 threads.
// thread micro-tile: 8 contiguous oc  x  7 contiguous positions.
template <int MODE>
__global__ void __launch_bounds__(224, 2)
conv_kernel(const float* __restrict__ x, const float* __restrict__ gc,
            const int* __restrict__ classes,
            const float* __restrict__ bn_gamma, const float* __restrict__ bn_beta,
            const float* __restrict__ bn_mean,  const float* __restrict__ bn_var,
            float* __restrict__ out) {
    int n  = blockIdx.y;
    int ob = blockIdx.x * 64;
    int tid = threadIdx.x;
    int oc_thr  = tid & 7;   // 0..7  -> ocs ob + oc_thr*8 + i
    int pos_thr = tid >> 3;  // 0..27 -> positions pos_thr*7 + m
    int p0 = pos_thr * 7;

    int base[7];
#pragma unroll
    for (int m = 0; m < 7; m++) {
        int p = p0 + m;
        base[m] = (p / 14) * 16 + (p % 14);
    }

    const float* Wg;
    bool gather = false;
    int mcount = 1;
    float invn = 1.0f;
    const int xbase = n * CC * HWP;
    if (MODE == 0) {
        if (classes[n] != 0) {
            Wg = g_Wc;
        } else {
            Wg = g_Wt;
            int c = g_cnt[n];
            if (c > 1) { gather = true; mcount = c; invn = g_inv[n]; }
        }
    } else {
        Wg = g_Wf;
    }

    __shared__ __align__(16) float Xs[TC * 256];      // padded 16x16 per channel
    __shared__ __align__(16) float Ws[TC * 9 * 64];   // [c_l*9+k][64 oc]

    float acc[8][7];
#pragma unroll
    for (int i = 0; i < 8; i++)
#pragma unroll
        for (int m = 0; m < 7; m++) acc[i][m] = 0.0f;

    for (int cb = 0; cb < CC; cb += TC) {
        __syncthreads();
        // weights: Wg[(cb*9 + ck)][ob + o], ck local in [0, TC*9)
        for (int idx = tid; idx < TC * 9 * 64; idx += 224) {
            int ck = idx >> 6;
            int o  = idx & 63;
            Ws[idx] = Wg[(cb * 9 + ck) * 256 + ob + o];
        }
        // input: zero-padded 16x16 tiles
        for (int idx = tid; idx < TC * 256; idx += 224) {
            int c_l = idx >> 8;
            int pp  = idx & 255;
            int yy = pp >> 4, xx = pp & 15;
            float v = 0.0f;
            if (yy >= 1 && yy < 15 && xx >= 1 && xx < 15) {
                int off = (cb + c_l) * HWP + (yy - 1) * 14 + (xx - 1);
                if (MODE == 0) {
                    if (!gather) {
                        v = x[xbase + off];
                    } else {
                        float s = 0.0f;
                        for (int t = 0; t < mcount; t++)
                            s += x[g_members[n * NN + t] * CC * HWP + off];
                        v = s * invn;
                    }
                } else {
                    int gi = xbase + off;
                    v = g_branch[gi] + x[gi] + gc[gi];
                }
            }
            Xs[idx] = v;
        }
        __syncthreads();

#pragma unroll 2
        for (int c_l = 0; c_l < TC; c_l++) {
#pragma unroll
            for (int k = 0; k < 9; k++) {
                float w[8];
                const float* wp = &Ws[(c_l * 9 + k) * 64 + oc_thr * 8];
                *(float4*)&w[0] = *(const float4*)wp;
                *(float4*)&w[4] = *(const float4*)(wp + 4);
                int dy = k / 3, dx = k % 3;
                int xoff = c_l * 256 + dy * 16 + dx;
                float xv[7];
#pragma unroll
                for (int m = 0; m < 7; m++) xv[m] = Xs[xoff + base[m]];
#pragma unroll
                for (int i = 0; i < 8; i++)
#pragma unroll
                    for (int m = 0; m < 7; m++)
                        acc[i][m] = fmaf(w[i], xv[m], acc[i][m]);
            }
        }
    }

    if (MODE == 0) {
#pragma unroll
        for (int i = 0; i < 8; i++) {
            float* po = &g_branch[xbase + (ob + oc_thr * 8 + i) * HWP + p0];
#pragma unroll
            for (int m = 0; m < 7; m++) po[m] = acc[i][m];
        }
    } else {
        float sc[8], sh[8];
#pragma unroll
        for (int i = 0; i < 8; i++) {
            int o = ob + oc_thr * 8 + i;
            float s = bn_gamma[o] * rsqrtf(bn_var[o] + 1e-5f);
            sc[i] = s;
            sh[i] = bn_beta[o] - bn_mean[o] * s;
        }
#pragma unroll
        for (int i = 0; i < 8; i++) {
            float* po = &out[xbase + (ob + oc_thr * 8 + i) * HWP + p0];
#pragma unroll
            for (int m = 0; m < 7; m++) {
                float v = fmaf(acc[i][m], sc[i], sh[i]);
                po[m] = fmaxf(v, 0.0f);
            }
        }
    }
}

// ---------------- launch ------------------------------------------------------
extern "C" void kernel_launch(void* const* d_in, const int* in_sizes, int n_in,
                              void* d_out, int out_size) {
    const float* x       = (const float*)d_in[0];
    const float* gc      = (const float*)d_in[1];
    const float* boxes   = (const float*)d_in[2];
    const int*   classes = (const int*)  d_in[3];
    const float* Wc3     = (const float*)d_in[4];
    const float* Wc1     = (const float*)d_in[5];
    const float* Wt3     = (const float*)d_in[6];
    const float* Wt1     = (const float*)d_in[7];
    const float* Wf3     = (const float*)d_in[8];
    const float* Wf1     = (const float*)d_in[9];
    const float* bg      = (const float*)d_in[10];
    const float* bb      = (const float*)d_in[11];
    const float* bm      = (const float*)d_in[12];
    const float* bv      = (const float*)d_in[13];
    float* out = (float*)d_out;

    mask_kernel<<<2, 256>>>(boxes);
    combine_kernel<<<dim3(72, 4, 3), 256>>>(Wc3, Wc1, Wt3, Wt1, Wf3, Wf1);
    conv_kernel<0><<<dim3(4, NN), 224>>>(x, gc, classes, bg, bb, bm, bv, nullptr);
    conv_kernel<1><<<dim3(4, NN), 224>>>(x, gc, classes, bg, bb, bm, bv, out);
}

// round 5
// speedup vs baseline: 1.1051x; 1.1051x over previous
#include <cuda_runtime.h>
#include <cuda_bf16.h>
#include <math.h>

#define NN 512
#define CC 256
#define HWP 196          // 14*14
#define CKTOT 2304       // C*9
#define TC 8             // input-channel chunk in smem

// ---------------- scratch (static device globals; no allocation) -------------
__device__ float g_Wc[CKTOT * CC];     // combined char weights   [ck][o]
__device__ float g_Wt[CKTOT * CC];     // combined text weights   [ck][o]
__device__ float g_Wf[CKTOT * CC];     // combined fuse weights   [ck][o]
__device__ float g_branch[NN * CC * HWP]; // branch conv output (103MB)
__device__ int   g_members[NN * NN];   // member lists per proposal
__device__ int   g_cnt[NN];
__device__ float g_inv[NN];

// ---------------- 1) box overlap mask / member lists -------------------------
__global__ void mask_kernel(const float* __restrict__ boxes) {
    int i = blockIdx.x * blockDim.x + threadIdx.x;
    if (i >= NN) return;
    float ax0 = boxes[i * 4 + 0], ay0 = boxes[i * 4 + 1];
    float ax1 = boxes[i * 4 + 2], ay1 = boxes[i * 4 + 3];
    int c = 0;
    for (int j = 0; j < NN; j++) {
        float bx0 = boxes[j * 4 + 0], by0 = boxes[j * 4 + 1];
        float bx1 = boxes[j * 4 + 2], by1 = boxes[j * 4 + 3];
        float ltx = fmaxf(ax0, bx0), lty = fmaxf(ay0, by0);
        float rbx = fminf(ax1, bx1), rby = fminf(ay1, by1);
        float w = fmaxf(rbx - ltx, 0.0f);
        float h = fmaxf(rby - lty, 0.0f);
        float inter = w * h;
        float areaj = (bx1 - bx0) * (by1 - by0);
        if (inter / areaj > 0.9f) { g_members[i * NN + c] = j; c++; }
    }
    g_cnt[i] = c;
    g_inv[i] = 1.0f / (float)c;
}

// ---------------- 2) fold conv1x1 into conv3x3 weights ------------------------
// Wo[ck][o] = sum_m W1[o][m] * W3[m][ck],   ck = c*9 + k
__global__ void combine_kernel(const float* __restrict__ Wc3, const float* __restrict__ Wc1,
                               const float* __restrict__ Wt3, const float* __restrict__ Wt1,
                               const float* __restrict__ Wf3, const float* __restrict__ Wf1) {
    const float *W3, *W1;
    float* Wo;
    if (blockIdx.z == 0)      { W3 = Wc3; W1 = Wc1; Wo = g_Wc; }
    else if (blockIdx.z == 1) { W3 = Wt3; W1 = Wt1; Wo = g_Wt; }
    else                      { W3 = Wf3; W1 = Wf1; Wo = g_Wf; }

    int ckb = blockIdx.x * 32;   // 72 tiles of 32 over 2304
    int ob  = blockIdx.y * 64;   // 4 tiles of 64 over 256
    int tid = threadIdx.x;       // 256 threads
    int ck_l = tid >> 3;         // 0..31
    int og   = tid & 7;          // 0..7 -> 8 contiguous outputs

    __shared__ __align__(16) float As[32 * 32];   // [m][ck]
    __shared__ __align__(16) float Bs[32 * 64];   // [m][o]

    float acc[8];
#pragma unroll
    for (int j = 0; j < 8; j++) acc[j] = 0.0f;

    for (int mb = 0; mb < 256; mb += 32) {
        __syncthreads();
        for (int idx = tid; idx < 1024; idx += 256) {
            int m = idx >> 5, ck = idx & 31;
            As[idx] = W3[(mb + m) * CKTOT + ckb + ck];
        }
        {
            int o  = tid & 63;
            int m8 = (tid >> 6) * 8;
#pragma unroll
            for (int mi = 0; mi < 8; mi++)
                Bs[(m8 + mi) * 64 + o] = W1[(ob + o) * 256 + mb + m8 + mi];
        }
        __syncthreads();
#pragma unroll
        for (int m = 0; m < 32; m++) {
            float a = As[m * 32 + ck_l];
            float b[8];
            *(float4*)&b[0] = *(const float4*)&Bs[m * 64 + og * 8];
            *(float4*)&b[4] = *(const float4*)&Bs[m * 64 + og * 8 + 4];
#pragma unroll
            for (int j = 0; j < 8; j++) acc[j] = fmaf(a, b[j], acc[j]);
        }
    }
    float* po = &Wo[(ckb + ck_l) * 256 + ob + og * 8];
    *(float4*)po       = *(const float4*)&acc[0];
    *(float4*)(po + 4) = *(const float4*)&acc[4];
}

// ---------------- 3) main conv3x3 kernel --------------------------------------
// MODE 0: branch conv. input = (class!=0) ? x[n] : gather-avg ; W = Wc or Wt ; out -> g_branch
// MODE 1: fuse conv.   input = g_branch[n] + x[n] + gc[n]     ; W = Wf        ; out -> d_out (BN+ReLU)
// grid (4 oc-tiles, 512 samples), block 224 threads.
// thread micro-tile: 4 contiguous oc  x  one full 14-wide output row.
// Per (c,dy): load whole padded input row (4x LDS.128, compile-time aligned),
// reuse across the 3 dx taps -> 21 LDS instr per 504 FMA per input channel.
template <int MODE>
__global__ void __launch_bounds__(224, 2)
conv_kernel(const float* __restrict__ x, const float* __restrict__ gc,
            const int* __restrict__ classes,
            const float* __restrict__ bn_gamma, const float* __restrict__ bn_beta,
            const float* __restrict__ bn_mean,  const float* __restrict__ bn_var,
            float* __restrict__ out) {
    int n  = blockIdx.y;
    int ob = blockIdx.x * 64;
    int tid = threadIdx.x;
    int oc_thr = tid & 15;   // 0..15 -> ocs ob + oc_thr*4 + i
    int row    = tid >> 4;   // 0..13 -> output row

    const float* Wg;
    bool gather = false;
    int mcount = 1;
    float invn = 1.0f;
    const int xbase = n * CC * HWP;
    if (MODE == 0) {
        if (classes[n] != 0) {
            Wg = g_Wc;
        } else {
            Wg = g_Wt;
            int c = g_cnt[n];
            if (c > 1) { gather = true; mcount = c; invn = g_inv[n]; }
        }
    } else {
        Wg = g_Wf;
    }

    __shared__ __align__(16) float Xs[TC * 256];      // padded 16x16 per channel
    __shared__ __align__(16) float Ws[TC * 9 * 64];   // [c_l*9+k][64 oc]

    float acc[4][14];
#pragma unroll
    for (int i = 0; i < 4; i++)
#pragma unroll
        for (int m = 0; m < 14; m++) acc[i][m] = 0.0f;

    for (int cb = 0; cb < CC; cb += TC) {
        __syncthreads();
        // weights: Wg[(cb*9 + ck)][ob + o], ck local in [0, TC*9)
        for (int idx = tid; idx < TC * 9 * 64; idx += 224) {
            int ck = idx >> 6;
            int o  = idx & 63;
            Ws[idx] = Wg[(cb * 9 + ck) * 256 + ob + o];
        }
        // input: zero-padded 16x16 tiles
        for (int idx = tid; idx < TC * 256; idx += 224) {
            int c_l = idx >> 8;
            int pp  = idx & 255;
            int yy = pp >> 4, xx = pp & 15;
            float v = 0.0f;
            if (yy >= 1 && yy < 15 && xx >= 1 && xx < 15) {
                int off = (cb + c_l) * HWP + (yy - 1) * 14 + (xx - 1);
                if (MODE == 0) {
                    if (!gather) {
                        v = x[xbase + off];
                    } else {
                        float s = 0.0f;
                        for (int t = 0; t < mcount; t++)
                            s += x[g_members[n * NN + t] * CC * HWP + off];
                        v = s * invn;
                    }
                } else {
                    int gi = xbase + off;
                    v = g_branch[gi] + x[gi] + gc[gi];
                }
            }
            Xs[idx] = v;
        }
        __syncthreads();

#pragma unroll
        for (int c_l = 0; c_l < TC; c_l++) {
#pragma unroll
            for (int dy = 0; dy < 3; dy++) {
                // full padded input row (output row 'row' reads padded rows row..row+2)
                float xr[16];
                const float* xp = &Xs[c_l * 256 + (row + dy) * 16];
                *(float4*)&xr[0]  = *(const float4*)(xp + 0);
                *(float4*)&xr[4]  = *(const float4*)(xp + 4);
                *(float4*)&xr[8]  = *(const float4*)(xp + 8);
                *(float4*)&xr[12] = *(const float4*)(xp + 12);
#pragma unroll
                for (int dx = 0; dx < 3; dx++) {
                    float w[4];
                    *(float4*)&w[0] =
                        *(const float4*)&Ws[(c_l * 9 + dy * 3 + dx) * 64 + oc_thr * 4];
#pragma unroll
                    for (int i = 0; i < 4; i++)
#pragma unroll
                        for (int m = 0; m < 14; m++)
                            acc[i][m] = fmaf(w[i], xr[dx + m], acc[i][m]);
                }
            }
        }
    }

    if (MODE == 0) {
#pragma unroll
        for (int i = 0; i < 4; i++) {
            float* po = &g_branch[xbase + (ob + oc_thr * 4 + i) * HWP + row * 14];
#pragma unroll
            for (int m = 0; m < 7; m++)
                *(float2*)(po + 2 * m) = make_float2(acc[i][2 * m], acc[i][2 * m + 1]);
        }
    } else {
        float sc[4], sh[4];
#pragma unroll
        for (int i = 0; i < 4; i++) {
            int o = ob + oc_thr * 4 + i;
            float s = bn_gamma[o] * rsqrtf(bn_var[o] + 1e-5f);
            sc[i] = s;
            sh[i] = bn_beta[o] - bn_mean[o] * s;
        }
#pragma unroll
        for (int i = 0; i < 4; i++) {
            float* po = &out[xbase + (ob + oc_thr * 4 + i) * HWP + row * 14];
#pragma unroll
            for (int m = 0; m < 7; m++) {
                float v0 = fmaxf(fmaf(acc[i][2 * m],     sc[i], sh[i]), 0.0f);
                float v1 = fmaxf(fmaf(acc[i][2 * m + 1], sc[i], sh[i]), 0.0f);
                *(float2*)(po + 2 * m) = make_float2(v0, v1);
            }
        }
    }
}

// ---------------- launch ------------------------------------------------------
extern "C" void kernel_launch(void* const* d_in, const int* in_sizes, int n_in,
                              void* d_out, int out_size) {
    const float* x       = (const float*)d_in[0];
    const float* gc      = (const float*)d_in[1];
    const float* boxes   = (const float*)d_in[2];
    const int*   classes = (const int*)  d_in[3];
    const float* Wc3     = (const float*)d_in[4];
    const float* Wc1     = (const float*)d_in[5];
    const float* Wt3     = (const float*)d_in[6];
    const float* Wt1     = (const float*)d_in[7];
    const float* Wf3     = (const float*)d_in[8];
    const float* Wf1     = (const float*)d_in[9];
    const float* bg      = (const float*)d_in[10];
    const float* bb      = (const float*)d_in[11];
    const float* bm      = (const float*)d_in[12];
    const float* bv      = (const float*)d_in[13];
    float* out = (float*)d_out;

    mask_kernel<<<2, 256>>>(boxes);
    combine_kernel<<<dim3(72, 4, 3), 256>>>(Wc3, Wc1, Wt3, Wt1, Wf3, Wf1);
    conv_kernel<0><<<dim3(4, NN), 224>>>(x, gc, classes, bg, bb, bm, bv, nullptr);
    conv_kernel<1><<<dim3(4, NN), 224>>>(x, gc, classes, bg, bb, bm, bv, out);
}

// round 6
// speedup vs baseline: 1.2002x; 1.0861x over previous
#include <cuda_runtime.h>
#include <cuda_bf16.h>
#include <math.h>

#define NN 512
#define CC 256
#define HWP 196          // 14*14
#define CKTOT 2304       // C*9
#define TC 8             // input-channel chunk in smem

typedef unsigned long long ull;

// packed dual FMA: d = a*b + c on two f32 lanes
#define FMA2(d, a, b, c) \
    asm("fma.rn.f32x2 %0, %1, %2, %3;" : "=l"(d) : "l"(a), "l"(b), "l"(c))
#define UNPACK2(lo, hi, v) \
    asm("mov.b64 {%0, %1}, %2;" : "=f"(lo), "=f"(hi) : "l"(v))

// ---------------- scratch (static device globals; no allocation) -------------
__device__ float g_Wc[CKTOT * CC];     // combined char weights   [ck][o]
__device__ float g_Wt[CKTOT * CC];     // combined text weights   [ck][o]
__device__ float g_Wf[CKTOT * CC];     // combined fuse weights   [ck][o]
__device__ float g_branch[NN * CC * HWP]; // branch conv output (103MB)
__device__ int   g_members[NN * NN];   // member lists per proposal
__device__ int   g_cnt[NN];
__device__ float g_inv[NN];

// ---------------- 1) box overlap mask / member lists -------------------------
__global__ void mask_kernel(const float* __restrict__ boxes) {
    int i = blockIdx.x * blockDim.x + threadIdx.x;
    if (i >= NN) return;
    float ax0 = boxes[i * 4 + 0], ay0 = boxes[i * 4 + 1];
    float ax1 = boxes[i * 4 + 2], ay1 = boxes[i * 4 + 3];
    int c = 0;
    for (int j = 0; j < NN; j++) {
        float bx0 = boxes[j * 4 + 0], by0 = boxes[j * 4 + 1];
        float bx1 = boxes[j * 4 + 2], by1 = boxes[j * 4 + 3];
        float ltx = fmaxf(ax0, bx0), lty = fmaxf(ay0, by0);
        float rbx = fminf(ax1, bx1), rby = fminf(ay1, by1);
        float w = fmaxf(rbx - ltx, 0.0f);
        float h = fmaxf(rby - lty, 0.0f);
        float inter = w * h;
        float areaj = (bx1 - bx0) * (by1 - by0);
        if (inter / areaj > 0.9f) { g_members[i * NN + c] = j; c++; }
    }
    g_cnt[i] = c;
    g_inv[i] = 1.0f / (float)c;
}

// ---------------- 2) fold conv1x1 into conv3x3 weights ------------------------
// Wo[ck][o] = sum_m W1[o][m] * W3[m][ck],   ck = c*9 + k
__global__ void combine_kernel(const float* __restrict__ Wc3, const float* __restrict__ Wc1,
                               const float* __restrict__ Wt3, const float* __restrict__ Wt1,
                               const float* __restrict__ Wf3, const float* __restrict__ Wf1) {
    const float *W3, *W1;
    float* Wo;
    if (blockIdx.z == 0)      { W3 = Wc3; W1 = Wc1; Wo = g_Wc; }
    else if (blockIdx.z == 1) { W3 = Wt3; W1 = Wt1; Wo = g_Wt; }
    else                      { W3 = Wf3; W1 = Wf1; Wo = g_Wf; }

    int ckb = blockIdx.x * 32;   // 72 tiles of 32 over 2304
    int ob  = blockIdx.y * 64;   // 4 tiles of 64 over 256
    int tid = threadIdx.x;       // 256 threads
    int ck_l = tid >> 3;         // 0..31
    int og   = tid & 7;          // 0..7 -> 8 contiguous outputs

    __shared__ __align__(16) float As[32 * 32];   // [m][ck]
    __shared__ __align__(16) float Bs[32 * 64];   // [m][o]

    float acc[8];
#pragma unroll
    for (int j = 0; j < 8; j++) acc[j] = 0.0f;

    for (int mb = 0; mb < 256; mb += 32) {
        __syncthreads();
        for (int idx = tid; idx < 1024; idx += 256) {
            int m = idx >> 5, ck = idx & 31;
            As[idx] = W3[(mb + m) * CKTOT + ckb + ck];
        }
        {
            int o  = tid & 63;
            int m8 = (tid >> 6) * 8;
#pragma unroll
            for (int mi = 0; mi < 8; mi++)
                Bs[(m8 + mi) * 64 + o] = W1[(ob + o) * 256 + mb + m8 + mi];
        }
        __syncthreads();
#pragma unroll
        for (int m = 0; m < 32; m++) {
            float a = As[m * 32 + ck_l];
            float b[8];
            *(float4*)&b[0] = *(const float4*)&Bs[m * 64 + og * 8];
            *(float4*)&b[4] = *(const float4*)&Bs[m * 64 + og * 8 + 4];
#pragma unroll
            for (int j = 0; j < 8; j++) acc[j] = fmaf(a, b[j], acc[j]);
        }
    }
    float* po = &Wo[(ckb + ck_l) * 256 + ob + og * 8];
    *(float4*)po       = *(const float4*)&acc[0];
    *(float4*)(po + 4) = *(const float4*)&acc[4];
}

// ---------------- 3) main conv3x3 kernel --------------------------------------
// MODE 0: branch conv. input = (class!=0) ? x[n] : gather-avg ; W = Wc or Wt ; out -> g_branch
// MODE 1: fuse conv.   input = g_branch[n] + x[n] + gc[n]     ; W = Wf        ; out -> d_out (BN+ReLU)
// grid (4 oc-tiles, 512 samples), block 224 threads.
// thread micro-tile: 4 oc x one full 14-wide output row, computed with packed
// fma.rn.f32x2: acc pairs over oc, x broadcast pairs (v,v) read straight from a
// value-duplicated smem tile (ld.shared.v2.u64 -> zero packing ALU).
template <int MODE>
__global__ void __launch_bounds__(224, 2)
conv_kernel(const float* __restrict__ x, const float* __restrict__ gc,
            const int* __restrict__ classes,
            const float* __restrict__ bn_gamma, const float* __restrict__ bn_beta,
            const float* __restrict__ bn_mean,  const float* __restrict__ bn_var,
            float* __restrict__ out) {
    int n  = blockIdx.y;
    int ob = blockIdx.x * 64;
    int tid = threadIdx.x;
    int oc_thr = tid & 15;   // 0..15 -> ocs ob + oc_thr*4 + i
    int row    = tid >> 4;   // 0..13 -> output row

    const float* Wg;
    bool gather = false;
    int mcount = 1;
    float invn = 1.0f;
    const int xbase = n * CC * HWP;
    if (MODE == 0) {
        if (classes[n] != 0) {
            Wg = g_Wc;
        } else {
            Wg = g_Wt;
            int c = g_cnt[n];
            if (c > 1) { gather = true; mcount = c; invn = g_inv[n]; }
        }
    } else {
        Wg = g_Wf;
    }

    // Xs: per channel, padded 16x16 tile with every value DUPLICATED:
    //   Xs[c*512 + (yy*16+xx)*2 + {0,1}] = v   -> 64-bit loads give (v,v) pairs
    __shared__ __align__(16) float Xs[TC * 512];
    __shared__ __align__(16) float Ws[TC * 9 * 64];   // [c_l*9+k][64 oc]

    ull acc2[2][14];   // [oc-pair j][m]; lo lane = oc 2j, hi lane = oc 2j+1
#pragma unroll
    for (int j = 0; j < 2; j++)
#pragma unroll
        for (int m = 0; m < 14; m++) acc2[j][m] = 0ULL;

    for (int cb = 0; cb < CC; cb += TC) {
        __syncthreads();
        // weights: Wg[(cb*9 + ck)][ob + o], ck local in [0, TC*9)
        for (int idx = tid; idx < TC * 9 * 64; idx += 224) {
            int ck = idx >> 6;
            int o  = idx & 63;
            Ws[idx] = Wg[(cb * 9 + ck) * 256 + ob + o];
        }
        // input: zero-padded 16x16 tiles, value-duplicated
        for (int idx = tid; idx < TC * 256; idx += 224) {
            int c_l = idx >> 8;
            int pp  = idx & 255;
            int yy = pp >> 4, xx = pp & 15;
            float v = 0.0f;
            if (yy >= 1 && yy < 15 && xx >= 1 && xx < 15) {
                int off = (cb + c_l) * HWP + (yy - 1) * 14 + (xx - 1);
                if (MODE == 0) {
                    if (!gather) {
                        v = x[xbase + off];
                    } else {
                        float s = 0.0f;
                        for (int t = 0; t < mcount; t++)
                            s += x[g_members[n * NN + t] * CC * HWP + off];
                        v = s * invn;
                    }
                } else {
                    int gi = xbase + off;
                    v = g_branch[gi] + x[gi] + gc[gi];
                }
            }
            *(float2*)&Xs[c_l * 512 + pp * 2] = make_float2(v, v);
        }
        __syncthreads();

#pragma unroll
        for (int c_l = 0; c_l < TC; c_l++) {
#pragma unroll
            for (int dy = 0; dy < 3; dy++) {
                // 16 broadcast pairs (v,v) for padded input row row+dy,
                // loaded as 8x ld.shared.v2.u64 (LDS.128)
                ull xp[16];
                const ulonglong2* xr =
                    (const ulonglong2*)&Xs[c_l * 512 + (row + dy) * 32];
#pragma unroll
                for (int q = 0; q < 8; q++) {
                    ulonglong2 t = xr[q];
                    xp[2 * q]     = t.x;
                    xp[2 * q + 1] = t.y;
                }
#pragma unroll
                for (int dx = 0; dx < 3; dx++) {
                    // 4 weights = 2 even-aligned pairs, straight from LDS.128
                    ulonglong2 wv = *(const ulonglong2*)
                        &Ws[(c_l * 9 + dy * 3 + dx) * 64 + oc_thr * 4];
#pragma unroll
                    for (int m = 0; m < 14; m++) {
                        FMA2(acc2[0][m], wv.x, xp[dx + m], acc2[0][m]);
                        FMA2(acc2[1][m], wv.y, xp[dx + m], acc2[1][m]);
                    }
                }
            }
        }
    }

    if (MODE == 0) {
#pragma unroll
        for (int j = 0; j < 2; j++) {
            float a0[14], a1[14];
#pragma unroll
            for (int m = 0; m < 14; m++) UNPACK2(a0[m], a1[m], acc2[j][m]);
            float* p0 = &g_branch[xbase + (ob + oc_thr * 4 + 2 * j) * HWP + row * 14];
            float* p1 = p0 + HWP;
#pragma unroll
            for (int m = 0; m < 7; m++) {
                *(float2*)(p0 + 2 * m) = make_float2(a0[2 * m], a0[2 * m + 1]);
                *(float2*)(p1 + 2 * m) = make_float2(a1[2 * m], a1[2 * m + 1]);
            }
        }
    } else {
#pragma unroll
        for (int j = 0; j < 2; j++) {
            int o0 = ob + oc_thr * 4 + 2 * j;
            float s0 = bn_gamma[o0] * rsqrtf(bn_var[o0] + 1e-5f);
            float h0 = bn_beta[o0] - bn_mean[o0] * s0;
            float s1 = bn_gamma[o0 + 1] * rsqrtf(bn_var[o0 + 1] + 1e-5f);
            float h1 = bn_beta[o0 + 1] - bn_mean[o0 + 1] * s1;
            float a0[14], a1[14];
#pragma unroll
            for (int m = 0; m < 14; m++) UNPACK2(a0[m], a1[m], acc2[j][m]);
            float* p0 = &out[xbase + o0 * HWP + row * 14];
            float* p1 = p0 + HWP;
#pragma unroll
            for (int m = 0; m < 7; m++) {
                float v00 = fmaxf(fmaf(a0[2 * m],     s0, h0), 0.0f);
                float v01 = fmaxf(fmaf(a0[2 * m + 1], s0, h0), 0.0f);
                float v10 = fmaxf(fmaf(a1[2 * m],     s1, h1), 0.0f);
                float v11 = fmaxf(fmaf(a1[2 * m + 1], s1, h1), 0.0f);
                *(float2*)(p0 + 2 * m) = make_float2(v00, v01);
                *(float2*)(p1 + 2 * m) = make_float2(v10, v11);
            }
        }
    }
}

// ---------------- launch ------------------------------------------------------
extern "C" void kernel_launch(void* const* d_in, const int* in_sizes, int n_in,
                              void* d_out, int out_size) {
    const float* x       = (const float*)d_in[0];
    const float* gc      = (const float*)d_in[1];
    const float* boxes   = (const float*)d_in[2];
    const int*   classes = (const int*)  d_in[3];
    const float* Wc3     = (const float*)d_in[4];
    const float* Wc1     = (const float*)d_in[5];
    const float* Wt3     = (const float*)d_in[6];
    const float* Wt1     = (const float*)d_in[7];
    const float* Wf3     = (const float*)d_in[8];
    const float* Wf1     = (const float*)d_in[9];
    const float* bg      = (const float*)d_in[10];
    const float* bb      = (const float*)d_in[11];
    const float* bm      = (const float*)d_in[12];
    const float* bv      = (const float*)d_in[13];
    float* out = (float*)d_out;

    mask_kernel<<<2, 256>>>(boxes);
    combine_kernel<<<dim3(72, 4, 3), 256>>>(Wc3, Wc1, Wt3, Wt1, Wf3, Wf1);
    conv_kernel<0><<<dim3(4, NN), 224>>>(x, gc, classes, bg, bb, bm, bv, nullptr);
    conv_kernel<1><<<dim3(4, NN), 224>>>(x, gc, classes, bg, bb, bm, bv, out);
}

// round 7
// speedup vs baseline: 2.1323x; 1.7766x over previous
#include <cuda_runtime.h>
#include <cuda_bf16.h>
#include <math.h>
#include <stdint.h>

#define NN 512
#define CC 256
#define HWP 196          // 14*14
#define KTOT 2304        // C*9

// ---------------- scratch (static device globals; no allocation) -------------
// reordered bf16 hi/lo weights: [oc][k'] with k' = (c/16)*144 + kk*16 + (c%16)
__device__ __nv_bfloat16 g_Whc[CC * KTOT], g_Wlc[CC * KTOT];
__device__ __nv_bfloat16 g_Wht[CC * KTOT], g_Wlt[CC * KTOT];
__device__ __nv_bfloat16 g_Whf[CC * KTOT], g_Wlf[CC * KTOT];
__device__ float g_branch[NN * CC * HWP]; // branch conv output (103MB)
__device__ int   g_members[NN * NN];
__device__ int   g_cnt[NN];
__device__ float g_inv[NN];

__device__ __forceinline__ uint32_t s2u(const void* p) {
    uint32_t a;
    asm("{ .reg .u64 t; cvta.to.shared.u64 t, %1; cvt.u32.u64 %0, t; }"
        : "=r"(a) : "l"(p));
    return a;
}

#define MMA_BF16(C, A, B)                                                      \
    asm volatile("mma.sync.aligned.m16n8k16.row.col.f32.bf16.bf16.f32 "        \
                 "{%0,%1,%2,%3}, {%4,%5,%6,%7}, {%8,%9}, {%0,%1,%2,%3};"       \
                 : "+f"((C)[0]), "+f"((C)[1]), "+f"((C)[2]), "+f"((C)[3])      \
                 : "r"((A)[0]), "r"((A)[1]), "r"((A)[2]), "r"((A)[3]),         \
                   "r"((B)[0]), "r"((B)[1]))

#define LDMATRIX_X4(A, addr)                                                   \
    asm volatile("ldmatrix.sync.aligned.m8n8.x4.shared.b16 {%0,%1,%2,%3}, [%4];" \
                 : "=r"((A)[0]), "=r"((A)[1]), "=r"((A)[2]), "=r"((A)[3])      \
                 : "r"(addr))

// ---------------- 1) box overlap mask / member lists -------------------------
__global__ void mask_kernel(const float* __restrict__ boxes) {
    int i = blockIdx.x * blockDim.x + threadIdx.x;
    if (i >= NN) return;
    float ax0 = boxes[i * 4 + 0], ay0 = boxes[i * 4 + 1];
    float ax1 = boxes[i * 4 + 2], ay1 = boxes[i * 4 + 3];
    int c = 0;
    for (int j = 0; j < NN; j++) {
        float bx0 = boxes[j * 4 + 0], by0 = boxes[j * 4 + 1];
        float bx1 = boxes[j * 4 + 2], by1 = boxes[j * 4 + 3];
        float ltx = fmaxf(ax0, bx0), lty = fmaxf(ay0, by0);
        float rbx = fminf(ax1, bx1), rby = fminf(ay1, by1);
        float w = fmaxf(rbx - ltx, 0.0f);
        float h = fmaxf(rby - lty, 0.0f);
        float inter = w * h;
        float areaj = (bx1 - bx0) * (by1 - by0);
        if (inter / areaj > 0.9f) { g_members[i * NN + c] = j; c++; }
    }
    g_cnt[i] = c;
    g_inv[i] = 1.0f / (float)c;
}

// ---------------- 2) fold conv1x1 into conv3x3, split bf16 hi/lo, reorder K ---
// W'[ck][o] = sum_m W1[o][m] * W3[m][ck]; stored as Whi/Wlo[o][k'(ck)]
__global__ void combine_kernel(const float* __restrict__ Wc3, const float* __restrict__ Wc1,
                               const float* __restrict__ Wt3, const float* __restrict__ Wt1,
                               const float* __restrict__ Wf3, const float* __restrict__ Wf1) {
    const float *W3, *W1;
    __nv_bfloat16 *Wh, *Wl;
    if (blockIdx.z == 0)      { W3 = Wc3; W1 = Wc1; Wh = g_Whc; Wl = g_Wlc; }
    else if (blockIdx.z == 1) { W3 = Wt3; W1 = Wt1; Wh = g_Wht; Wl = g_Wlt; }
    else                      { W3 = Wf3; W1 = Wf1; Wh = g_Whf; Wl = g_Wlf; }

    int ckb = blockIdx.x * 32;
    int ob  = blockIdx.y * 64;
    int tid = threadIdx.x;
    int ck_l = tid >> 3;
    int og   = tid & 7;

    __shared__ __align__(16) float As[32 * 32];
    __shared__ __align__(16) float Bs[32 * 64];

    float acc[8];
#pragma unroll
    for (int j = 0; j < 8; j++) acc[j] = 0.0f;

    for (int mb = 0; mb < 256; mb += 32) {
        __syncthreads();
        for (int idx = tid; idx < 1024; idx += 256) {
            int m = idx >> 5, ck = idx & 31;
            As[idx] = W3[(mb + m) * KTOT + ckb + ck];
        }
        {
            int o  = tid & 63;
            int m8 = (tid >> 6) * 8;
#pragma unroll
            for (int mi = 0; mi < 8; mi++)
                Bs[(m8 + mi) * 64 + o] = W1[(ob + o) * 256 + mb + m8 + mi];
        }
        __syncthreads();
#pragma unroll
        for (int m = 0; m < 32; m++) {
            float a = As[m * 32 + ck_l];
            float b[8];
            *(float4*)&b[0] = *(const float4*)&Bs[m * 64 + og * 8];
            *(float4*)&b[4] = *(const float4*)&Bs[m * 64 + og * 8 + 4];
#pragma unroll
            for (int j = 0; j < 8; j++) acc[j] = fmaf(a, b[j], acc[j]);
        }
    }
    int ck = ckb + ck_l;
    int c = ck / 9, kk = ck % 9;
    int ckp = (c >> 4) * 144 + kk * 16 + (c & 15);
#pragma unroll
    for (int j = 0; j < 8; j++) {
        int oc = ob + og * 8 + j;
        float w = acc[j];
        __nv_bfloat16 h = __float2bfloat16(w);
        __nv_bfloat16 l = __float2bfloat16(w - __bfloat162float(h));
        Wh[oc * KTOT + ckp] = h;
        Wl[oc * KTOT + ckp] = l;
    }
}

// ---------------- 3) conv3x3 as implicit-im2col GEMM on tensor cores ---------
// D[pos 224pad, oc 128] per CTA; grid (2 oc-halves, 512 samples), 512 threads.
// 16 warps: warpM = warp&1 (112 pos), warpN = warp>>1 (16 oc).
// Per 16-channel chunk: smem padded input tile Xh/Xl[288 posrows][24 ch-slots],
// 9 k-steps (one 3x3 tap each, 16 channels = k16). A via ldmatrix.x4 (48B row
// stride = conflict-free), B via LDG bf16-pairs from reordered W. 3 MMA variants
// (hi*hi + lo*hi + hi*lo) accumulate fp32.
template <int MODE>
__global__ void __launch_bounds__(512, 1)
conv_mma(const float* __restrict__ x, const float* __restrict__ gc,
         const int* __restrict__ classes,
         const float* __restrict__ bn_gamma, const float* __restrict__ bn_beta,
         const float* __restrict__ bn_mean,  const float* __restrict__ bn_var,
         float* __restrict__ out) {
    const int n  = blockIdx.y;
    const int ob = blockIdx.x * 128;
    const int tid = threadIdx.x;
    const int lane = tid & 31;
    const int warp = tid >> 5;
    const int wM = warp & 1;
    const int wN = warp >> 1;
    const int xbase = n * CC * HWP;

    const __nv_bfloat16 *Wh, *Wl;
    bool gather = false;
    int mcount = 1;
    float invn = 1.0f;
    if (MODE == 0) {
        if (classes[n] != 0) { Wh = g_Whc; Wl = g_Wlc; }
        else {
            Wh = g_Wht; Wl = g_Wlt;
            int c = g_cnt[n];
            if (c > 1) { gather = true; mcount = c; invn = g_inv[n]; }
        }
    } else { Wh = g_Whf; Wl = g_Wlf; }

    __shared__ __align__(16) __nv_bfloat16 Xh[288 * 24];
    __shared__ __align__(16) __nv_bfloat16 Xl[288 * 24];
    const uint32_t xh_base = s2u(Xh);
    const uint32_t xl_base = s2u(Xl);

    // per-lane A-tile row bases: output pos m -> input-tile row r*16+q
    int pb[7];
#pragma unroll
    for (int i = 0; i < 7; i++) {
        int m = wM * 112 + i * 16 + (lane & 15);
        pb[i] = (m / 14) * 16 + (m % 14);
    }
    // B pointers: this thread's oc rows (nt=0,1)
    const int oc_n0 = ob + wN * 16 + (lane >> 2);
    const __nv_bfloat16* wh0 = Wh + (size_t)oc_n0 * KTOT;
    const __nv_bfloat16* wl0 = Wl + (size_t)oc_n0 * KTOT;
    const __nv_bfloat16* wh1 = wh0 + 8 * KTOT;
    const __nv_bfloat16* wl1 = wl0 + 8 * KTOT;
    const int kp = 2 * (lane & 3);

    float acc[7][2][4];
#pragma unroll
    for (int i = 0; i < 7; i++)
#pragma unroll
        for (int t = 0; t < 2; t++)
#pragma unroll
            for (int v = 0; v < 4; v++) acc[i][t][v] = 0.0f;

    for (int ch16 = 0; ch16 < 16; ch16++) {
        // ---- fill Xh/Xl: warp w handles channel w of this chunk ----
        {
            int cglob = ch16 * 16 + warp;
            int cb = xbase + cglob * HWP;
#pragma unroll
            for (int rep = 0; rep < 9; rep++) {
                int pr = rep * 32 + lane;       // 0..287
                int iy = pr >> 4, ix = pr & 15;
                float v = 0.0f;
                if (iy >= 1 && iy < 15 && ix >= 1 && ix < 15) {
                    int off = (iy - 1) * 14 + (ix - 1);
                    if (MODE == 0) {
                        if (!gather) v = x[cb + off];
                        else {
                            float s = 0.0f;
                            for (int t = 0; t < mcount; t++)
                                s += x[g_members[n * NN + t] * CC * HWP + cglob * HWP + off];
                            v = s * invn;
                        }
                    } else {
                        int gi = cb + off;
                        v = g_branch[gi] + x[gi] + gc[gi];
                    }
                }
                __nv_bfloat16 h = __float2bfloat16(v);
                Xh[pr * 24 + warp] = h;
                Xl[pr * 24 + warp] = __float2bfloat16(v - __bfloat162float(h));
            }
        }
        __syncthreads();

        const int kg = ch16 * 144 + kp;
        // prefetch B for kk=0
        uint32_t pbh[2][2], pbl[2][2];
        pbh[0][0] = *(const uint32_t*)(wh0 + kg);
        pbh[0][1] = *(const uint32_t*)(wh0 + kg + 8);
        pbh[1][0] = *(const uint32_t*)(wh1 + kg);
        pbh[1][1] = *(const uint32_t*)(wh1 + kg + 8);
        pbl[0][0] = *(const uint32_t*)(wl0 + kg);
        pbl[0][1] = *(const uint32_t*)(wl0 + kg + 8);
        pbl[1][0] = *(const uint32_t*)(wl1 + kg);
        pbl[1][1] = *(const uint32_t*)(wl1 + kg + 8);

#pragma unroll
        for (int kk = 0; kk < 9; kk++) {
            uint32_t cbh[2][2], cbl[2][2];
#pragma unroll
            for (int t = 0; t < 2; t++) {
                cbh[t][0] = pbh[t][0]; cbh[t][1] = pbh[t][1];
                cbl[t][0] = pbl[t][0]; cbl[t][1] = pbl[t][1];
            }
            if (kk < 8) {
                int kg2 = kg + (kk + 1) * 16;
                pbh[0][0] = *(const uint32_t*)(wh0 + kg2);
                pbh[0][1] = *(const uint32_t*)(wh0 + kg2 + 8);
                pbh[1][0] = *(const uint32_t*)(wh1 + kg2);
                pbh[1][1] = *(const uint32_t*)(wh1 + kg2 + 8);
                pbl[0][0] = *(const uint32_t*)(wl0 + kg2);
                pbl[0][1] = *(const uint32_t*)(wl0 + kg2 + 8);
                pbl[1][0] = *(const uint32_t*)(wl1 + kg2);
                pbl[1][1] = *(const uint32_t*)(wl1 + kg2 + 8);
            }
            const int koff = (kk / 3) * 16 + (kk % 3);   // dy*16+dx
            const uint32_t half = (lane >> 4) * 16;
#pragma unroll
            for (int i = 0; i < 7; i++) {
                uint32_t rowoff = (uint32_t)(pb[i] + koff) * 48 + half;
                uint32_t ah[4], al[4];
                LDMATRIX_X4(ah, xh_base + rowoff);
                LDMATRIX_X4(al, xl_base + rowoff);
#pragma unroll
                for (int t = 0; t < 2; t++) {
                    MMA_BF16(acc[i][t], ah, cbh[t]);
                    MMA_BF16(acc[i][t], al, cbh[t]);
                    MMA_BF16(acc[i][t], ah, cbl[t]);
                }
            }
        }
        __syncthreads();
    }

    // ---- epilogue ----
    if (MODE == 0) {
#pragma unroll
        for (int i = 0; i < 7; i++) {
            int m0 = wM * 112 + i * 16 + (lane >> 2);
#pragma unroll
            for (int t = 0; t < 2; t++) {
                int oc0 = ob + wN * 16 + t * 8 + 2 * (lane & 3);
                float* p = &g_branch[xbase + oc0 * HWP];
                if (m0 < HWP) {
                    p[m0]       = acc[i][t][0];
                    p[HWP + m0] = acc[i][t][1];
                }
                if (m0 + 8 < HWP) {
                    p[m0 + 8]       = acc[i][t][2];
                    p[HWP + m0 + 8] = acc[i][t][3];
                }
            }
        }
    } else {
        float sc[2][2], sh[2][2];
#pragma unroll
        for (int t = 0; t < 2; t++) {
#pragma unroll
            for (int j = 0; j < 2; j++) {
                int oc = ob + wN * 16 + t * 8 + 2 * (lane & 3) + j;
                float s = bn_gamma[oc] * rsqrtf(bn_var[oc] + 1e-5f);
                sc[t][j] = s;
                sh[t][j] = bn_beta[oc] - bn_mean[oc] * s;
            }
        }
#pragma unroll
        for (int i = 0; i < 7; i++) {
            int m0 = wM * 112 + i * 16 + (lane >> 2);
#pragma unroll
            for (int t = 0; t < 2; t++) {
                int oc0 = ob + wN * 16 + t * 8 + 2 * (lane & 3);
                float* p = &out[xbase + oc0 * HWP];
                if (m0 < HWP) {
                    p[m0]       = fmaxf(fmaf(acc[i][t][0], sc[t][0], sh[t][0]), 0.0f);
                    p[HWP + m0] = fmaxf(fmaf(acc[i][t][1], sc[t][1], sh[t][1]), 0.0f);
                }
                if (m0 + 8 < HWP) {
                    p[m0 + 8]       = fmaxf(fmaf(acc[i][t][2], sc[t][0], sh[t][0]), 0.0f);
                    p[HWP + m0 + 8] = fmaxf(fmaf(acc[i][t][3], sc[t][1], sh[t][1]), 0.0f);
                }
            }
        }
    }
}

// ---------------- launch ------------------------------------------------------
extern "C" void kernel_launch(void* const* d_in, const int* in_sizes, int n_in,
                              void* d_out, int out_size) {
    const float* x       = (const float*)d_in[0];
    const float* gc      = (const float*)d_in[1];
    const float* boxes   = (const float*)d_in[2];
    const int*   classes = (const int*)  d_in[3];
    const float* Wc3     = (const float*)d_in[4];
    const float* Wc1     = (const float*)d_in[5];
    const float* Wt3     = (const float*)d_in[6];
    const float* Wt1     = (const float*)d_in[7];
    const float* Wf3     = (const float*)d_in[8];
    const float* Wf1     = (const float*)d_in[9];
    const float* bg      = (const float*)d_in[10];
    const float* bb      = (const float*)d_in[11];
    const float* bm      = (const float*)d_in[12];
    const float* bv      = (const float*)d_in[13];
    float* out = (float*)d_out;

    mask_kernel<<<2, 256>>>(boxes);
    combine_kernel<<<dim3(72, 4, 3), 256>>>(Wc3, Wc1, Wt3, Wt1, Wf3, Wf1);
    conv_mma<0><<<dim3(2, NN), 512>>>(x, gc, classes, bg, bb, bm, bv, nullptr);
    conv_mma<1><<<dim3(2, NN), 512>>>(x, gc, classes, bg, bb, bm, bv, out);
}

// round 8
// speedup vs baseline: 2.8186x; 1.3219x over previous
#include <cuda_runtime.h>
#include <cuda_bf16.h>
#include <cuda_fp16.h>
#include <math.h>
#include <stdint.h>

#define NN 512
#define CC 256
#define HWP 196          // 14*14
#define KTOT 2304        // C*9

// ---------------- scratch (static device globals; no allocation) -------------
// reordered fp16 hi/lo weights: [oc][k'] with k' = (c/16)*144 + kk*16 + (c%16)
__device__ __half g_Whc[CC * KTOT], g_Wlc[CC * KTOT];
__device__ __half g_Wht[CC * KTOT], g_Wlt[CC * KTOT];
__device__ __half g_Whf[CC * KTOT], g_Wlf[CC * KTOT];
__device__ float g_branch[NN * CC * HWP]; // branch conv output (103MB)
__device__ int   g_members[NN * NN];
__device__ int   g_cnt[NN];
__device__ float g_inv[NN];

__device__ __forceinline__ uint32_t s2u(const void* p) {
    uint32_t a;
    asm("{ .reg .u64 t; cvta.to.shared.u64 t, %1; cvt.u32.u64 %0, t; }"
        : "=r"(a) : "l"(p));
    return a;
}

#define MMA_F16(C, A, B)                                                       \
    asm volatile("mma.sync.aligned.m16n8k16.row.col.f32.f16.f16.f32 "          \
                 "{%0,%1,%2,%3}, {%4,%5,%6,%7}, {%8,%9}, {%0,%1,%2,%3};"       \
                 : "+f"((C)[0]), "+f"((C)[1]), "+f"((C)[2]), "+f"((C)[3])      \
                 : "r"((A)[0]), "r"((A)[1]), "r"((A)[2]), "r"((A)[3]),         \
                   "r"((B)[0]), "r"((B)[1]))

#define LDMATRIX_X4(A, addr)                                                   \
    asm volatile("ldmatrix.sync.aligned.m8n8.x4.shared.b16 {%0,%1,%2,%3}, [%4];" \
                 : "=r"((A)[0]), "=r"((A)[1]), "=r"((A)[2]), "=r"((A)[3])      \
                 : "r"(addr))

// ---------------- 1) box overlap mask / member lists -------------------------
__global__ void mask_kernel(const float* __restrict__ boxes) {
    int i = blockIdx.x * blockDim.x + threadIdx.x;
    if (i >= NN) return;
    float ax0 = boxes[i * 4 + 0], ay0 = boxes[i * 4 + 1];
    float ax1 = boxes[i * 4 + 2], ay1 = boxes[i * 4 + 3];
    int c = 0;
    for (int j = 0; j < NN; j++) {
        float bx0 = boxes[j * 4 + 0], by0 = boxes[j * 4 + 1];
        float bx1 = boxes[j * 4 + 2], by1 = boxes[j * 4 + 3];
        float ltx = fmaxf(ax0, bx0), lty = fmaxf(ay0, by0);
        float rbx = fminf(ax1, bx1), rby = fminf(ay1, by1);
        float w = fmaxf(rbx - ltx, 0.0f);
        float h = fmaxf(rby - lty, 0.0f);
        float inter = w * h;
        float areaj = (bx1 - bx0) * (by1 - by0);
        if (inter / areaj > 0.9f) { g_members[i * NN + c] = j; c++; }
    }
    g_cnt[i] = c;
    g_inv[i] = 1.0f / (float)c;
}

// ---------------- 2) fold conv1x1 into conv3x3, split fp16 hi/lo, reorder K ---
// W'[ck][o] = sum_m W1[o][m] * W3[m][ck]; stored as Whi/Wlo[o][k'(ck)]
__global__ void combine_kernel(const float* __restrict__ Wc3, const float* __restrict__ Wc1,
                               const float* __restrict__ Wt3, const float* __restrict__ Wt1,
                               const float* __restrict__ Wf3, const float* __restrict__ Wf1) {
    const float *W3, *W1;
    __half *Wh, *Wl;
    if (blockIdx.z == 0)      { W3 = Wc3; W1 = Wc1; Wh = g_Whc; Wl = g_Wlc; }
    else if (blockIdx.z == 1) { W3 = Wt3; W1 = Wt1; Wh = g_Wht; Wl = g_Wlt; }
    else                      { W3 = Wf3; W1 = Wf1; Wh = g_Whf; Wl = g_Wlf; }

    int ckb = blockIdx.x * 32;
    int ob  = blockIdx.y * 64;
    int tid = threadIdx.x;
    int ck_l = tid >> 3;
    int og   = tid & 7;

    __shared__ __align__(16) float As[32 * 32];
    __shared__ __align__(16) float Bs[32 * 64];

    float acc[8];
#pragma unroll
    for (int j = 0; j < 8; j++) acc[j] = 0.0f;

    for (int mb = 0; mb < 256; mb += 32) {
        __syncthreads();
        for (int idx = tid; idx < 1024; idx += 256) {
            int m = idx >> 5, ck = idx & 31;
            As[idx] = W3[(mb + m) * KTOT + ckb + ck];
        }
        {
            int o  = tid & 63;
            int m8 = (tid >> 6) * 8;
#pragma unroll
            for (int mi = 0; mi < 8; mi++)
                Bs[(m8 + mi) * 64 + o] = W1[(ob + o) * 256 + mb + m8 + mi];
        }
        __syncthreads();
#pragma unroll
        for (int m = 0; m < 32; m++) {
            float a = As[m * 32 + ck_l];
            float b[8];
            *(float4*)&b[0] = *(const float4*)&Bs[m * 64 + og * 8];
            *(float4*)&b[4] = *(const float4*)&Bs[m * 64 + og * 8 + 4];
#pragma unroll
            for (int j = 0; j < 8; j++) acc[j] = fmaf(a, b[j], acc[j]);
        }
    }
    int ck = ckb + ck_l;
    int c = ck / 9, kk = ck % 9;
    int ckp = (c >> 4) * 144 + kk * 16 + (c & 15);
#pragma unroll
    for (int j = 0; j < 8; j++) {
        int oc = ob + og * 8 + j;
        float w = acc[j];
        __half h = __float2half(w);
        __half l = __float2half(w - __half2float(h));
        Wh[oc * KTOT + ckp] = h;
        Wl[oc * KTOT + ckp] = l;
    }
}

// ---------------- 3) conv3x3 as implicit-im2col GEMM on tensor cores ---------
// D[pos 224pad, oc 128] per CTA; grid (2 oc-halves, 512 samples), 512 threads.
// 16 warps: warpM = warp&1 (112 pos), warpN = warp>>1 (16 oc).
// fp16: x single-precision-fp16, W hi/lo fp16 -> per A-tile: 1 ldmatrix + 2 MMA.
// Double-buffered channel chunks: stage next chunk's GMEM values in registers
// before the MMA block, STS after it; one __syncthreads per chunk.
template <int MODE>
__global__ void __launch_bounds__(512, 1)
conv_mma(const float* __restrict__ x, const float* __restrict__ gc,
         const int* __restrict__ classes,
         const float* __restrict__ bn_gamma, const float* __restrict__ bn_beta,
         const float* __restrict__ bn_mean,  const float* __restrict__ bn_var,
         float* __restrict__ out) {
    const int n  = blockIdx.y;
    const int ob = blockIdx.x * 128;
    const int tid = threadIdx.x;
    const int lane = tid & 31;
    const int warp = tid >> 5;
    const int wM = warp & 1;
    const int wN = warp >> 1;
    const int xbase = n * CC * HWP;

    const __half *Wh, *Wl;
    bool gather = false;
    int mcount = 1;
    float invn = 1.0f;
    if (MODE == 0) {
        if (classes[n] != 0) { Wh = g_Whc; Wl = g_Wlc; }
        else {
            Wh = g_Wht; Wl = g_Wlt;
            int c = g_cnt[n];
            if (c > 1) { gather = true; mcount = c; invn = g_inv[n]; }
        }
    } else { Wh = g_Whf; Wl = g_Wlf; }

    __shared__ __align__(16) __half Xs[2][288 * 24];

    // per-lane A-tile row bases: output pos m -> input-tile row r*16+q
    int pb[7];
#pragma unroll
    for (int i = 0; i < 7; i++) {
        int m = wM * 112 + i * 16 + (lane & 15);
        pb[i] = (m / 14) * 16 + (m % 14);
    }
    // B pointers: this thread's oc rows (nt=0,1)
    const int oc_n0 = ob + wN * 16 + (lane >> 2);
    const __half* wh0 = Wh + (size_t)oc_n0 * KTOT;
    const __half* wl0 = Wl + (size_t)oc_n0 * KTOT;
    const __half* wh1 = wh0 + 8 * KTOT;
    const __half* wl1 = wl0 + 8 * KTOT;
    const int kp = 2 * (lane & 3);

    float acc[7][2][4];
#pragma unroll
    for (int i = 0; i < 7; i++)
#pragma unroll
        for (int t = 0; t < 2; t++)
#pragma unroll
            for (int v = 0; v < 4; v++) acc[i][t][v] = 0.0f;

    // ---- per-warp chunk loader: warp w handles channel w of the chunk ----
    float vstage[9];
    auto load_vals = [&](int ch16) {
        int cglob = ch16 * 16 + warp;
        int cb = xbase + cglob * HWP;
#pragma unroll
        for (int rep = 0; rep < 9; rep++) {
            int pr = rep * 32 + lane;       // 0..287 over 18x16 padded tile
            int iy = pr >> 4, ix = pr & 15;
            float v = 0.0f;
            if (iy >= 1 && iy < 15 && ix >= 1 && ix < 15) {
                int off = (iy - 1) * 14 + (ix - 1);
                if (MODE == 0) {
                    if (!gather) v = x[cb + off];
                    else {
                        float s = 0.0f;
                        for (int t = 0; t < mcount; t++)
                            s += x[g_members[n * NN + t] * CC * HWP + cglob * HWP + off];
                        v = s * invn;
                    }
                } else {
                    int gi = cb + off;
                    v = g_branch[gi] + x[gi] + gc[gi];
                }
            }
            vstage[rep] = v;
        }
    };
    auto store_vals = [&](int buf) {
#pragma unroll
        for (int rep = 0; rep < 9; rep++) {
            int pr = rep * 32 + lane;
            Xs[buf][pr * 24 + warp] = __float2half(vstage[rep]);
        }
    };

    load_vals(0);
    store_vals(0);
    __syncthreads();

    for (int ch16 = 0; ch16 < 16; ch16++) {
        const int buf = ch16 & 1;
        const uint32_t xh_base = s2u(Xs[buf]);

        if (ch16 < 15) load_vals(ch16 + 1);   // LDGs in flight under the MMAs

        const int kg = ch16 * 144 + kp;
        // prefetch B for kk=0
        uint32_t pbh[2][2], pbl[2][2];
        pbh[0][0] = *(const uint32_t*)(wh0 + kg);
        pbh[0][1] = *(const uint32_t*)(wh0 + kg + 8);
        pbh[1][0] = *(const uint32_t*)(wh1 + kg);
        pbh[1][1] = *(const uint32_t*)(wh1 + kg + 8);
        pbl[0][0] = *(const uint32_t*)(wl0 + kg);
        pbl[0][1] = *(const uint32_t*)(wl0 + kg + 8);
        pbl[1][0] = *(const uint32_t*)(wl1 + kg);
        pbl[1][1] = *(const uint32_t*)(wl1 + kg + 8);

#pragma unroll
        for (int kk = 0; kk < 9; kk++) {
            uint32_t cbh[2][2], cbl[2][2];
#pragma unroll
            for (int t = 0; t < 2; t++) {
                cbh[t][0] = pbh[t][0]; cbh[t][1] = pbh[t][1];
                cbl[t][0] = pbl[t][0]; cbl[t][1] = pbl[t][1];
            }
            if (kk < 8) {
                int kg2 = kg + (kk + 1) * 16;
                pbh[0][0] = *(const uint32_t*)(wh0 + kg2);
                pbh[0][1] = *(const uint32_t*)(wh0 + kg2 + 8);
                pbh[1][0] = *(const uint32_t*)(wh1 + kg2);
                pbh[1][1] = *(const uint32_t*)(wh1 + kg2 + 8);
                pbl[0][0] = *(const uint32_t*)(wl0 + kg2);
                pbl[0][1] = *(const uint32_t*)(wl0 + kg2 + 8);
                pbl[1][0] = *(const uint32_t*)(wl1 + kg2);
                pbl[1][1] = *(const uint32_t*)(wl1 + kg2 + 8);
            }
            const int koff = (kk / 3) * 16 + (kk % 3);   // dy*16+dx
            const uint32_t half = (lane >> 4) * 16;
#pragma unroll
            for (int i = 0; i < 7; i++) {
                uint32_t rowoff = (uint32_t)(pb[i] + koff) * 48 + half;
                uint32_t ah[4];
                LDMATRIX_X4(ah, xh_base + rowoff);
#pragma unroll
                for (int t = 0; t < 2; t++) {
                    MMA_F16(acc[i][t], ah, cbh[t]);
                    MMA_F16(acc[i][t], ah, cbl[t]);
                }
            }
        }

        if (ch16 < 15) store_vals(buf ^ 1);
        __syncthreads();
    }

    // ---- epilogue ----
    if (MODE == 0) {
#pragma unroll
        for (int i = 0; i < 7; i++) {
            int m0 = wM * 112 + i * 16 + (lane >> 2);
#pragma unroll
            for (int t = 0; t < 2; t++) {
                int oc0 = ob + wN * 16 + t * 8 + 2 * (lane & 3);
                float* p = &g_branch[xbase + oc0 * HWP];
                if (m0 < HWP) {
                    p[m0]       = acc[i][t][0];
                    p[HWP + m0] = acc[i][t][1];
                }
                if (m0 + 8 < HWP) {
                    p[m0 + 8]       = acc[i][t][2];
                    p[HWP + m0 + 8] = acc[i][t][3];
                }
            }
        }
    } else {
        float sc[2][2], sh[2][2];
#pragma unroll
        for (int t = 0; t < 2; t++) {
#pragma unroll
            for (int j = 0; j < 2; j++) {
                int oc = ob + wN * 16 + t * 8 + 2 * (lane & 3) + j;
                float s = bn_gamma[oc] * rsqrtf(bn_var[oc] + 1e-5f);
                sc[t][j] = s;
                sh[t][j] = bn_beta[oc] - bn_mean[oc] * s;
            }
        }
#pragma unroll
        for (int i = 0; i < 7; i++) {
            int m0 = wM * 112 + i * 16 + (lane >> 2);
#pragma unroll
            for (int t = 0; t < 2; t++) {
                int oc0 = ob + wN * 16 + t * 8 + 2 * (lane & 3);
                float* p = &out[xbase + oc0 * HWP];
                if (m0 < HWP) {
                    p[m0]       = fmaxf(fmaf(acc[i][t][0], sc[t][0], sh[t][0]), 0.0f);
                    p[HWP + m0] = fmaxf(fmaf(acc[i][t][1], sc[t][1], sh[t][1]), 0.0f);
                }
                if (m0 + 8 < HWP) {
                    p[m0 + 8]       = fmaxf(fmaf(acc[i][t][2], sc[t][0], sh[t][0]), 0.0f);
                    p[HWP + m0 + 8] = fmaxf(fmaf(acc[i][t][3], sc[t][1], sh[t][1]), 0.0f);
                }
            }
        }
    }
}

// ---------------- launch ------------------------------------------------------
extern "C" void kernel_launch(void* const* d_in, const int* in_sizes, int n_in,
                              void* d_out, int out_size) {
    const float* x       = (const float*)d_in[0];
    const float* gc      = (const float*)d_in[1];
    const float* boxes   = (const float*)d_in[2];
    const int*   classes = (const int*)  d_in[3];
    const float* Wc3     = (const float*)d_in[4];
    const float* Wc1     = (const float*)d_in[5];
    const float* Wt3     = (const float*)d_in[6];
    const float* Wt1     = (const float*)d_in[7];
    const float* Wf3     = (const float*)d_in[8];
    const float* Wf1     = (const float*)d_in[9];
    const float* bg      = (const float*)d_in[10];
    const float* bb      = (const float*)d_in[11];
    const float* bm      = (const float*)d_in[12];
    const float* bv      = (const float*)d_in[13];
    float* out = (float*)d_out;

    mask_kernel<<<2, 256>>>(boxes);
    combine_kernel<<<dim3(72, 4, 3), 256>>>(Wc3, Wc1, Wt3, Wt1, Wf3, Wf1);
    conv_mma<0><<<dim3(2, NN), 512>>>(x, gc, classes, bg, bb, bm, bv, nullptr);
    conv_mma<1><<<dim3(2, NN), 512>>>(x, gc, classes, bg, bb, bm, bv, out);
}